// round 14
// baseline (speedup 1.0000x reference)
#include <cuda_runtime.h>
#include <cuda_bf16.h>
#include <cstdint>
#include <cstddef>

// Problem constants
#define B_N 131072
#define H_N 256
#define C_N 8

// ---------------------------------------------------------------------------
// Device globals (no allocations allowed)
// ---------------------------------------------------------------------------
__device__ int g_cnt[C_N];
__device__ int g_rows[C_N * B_N];
// Transposed bf16 3-term splits of [W1 ; Wc1[0..7]] as [9][N=256][K=256], K-major
__device__ __nv_bfloat16 g_Bh[9 * 65536];
__device__ __nv_bfloat16 g_Bm[9 * 65536];
__device__ __nv_bfloat16 g_Bl[9 * 65536];

// ---------------------------------------------------------------------------
// Helpers
// ---------------------------------------------------------------------------
__device__ __forceinline__ uint32_t smem_to_u32(const void* p) {
    uint32_t a;
    asm("{ .reg .u64 t; cvta.to.shared.u64 t, %1; cvt.u32.u64 %0, t; }" : "=r"(a) : "l"(p));
    return a;
}
#define SMEM_SWIZZLE_128B(o) ((o) ^ (((o) >> 3) & 0x70))

// ldmatrix x4 (sm_75+ baseline PTX — survives non-'a' targets)
__device__ __forceinline__ void ldsm_x4(uint32_t* r, uint32_t addr) {
    asm volatile("ldmatrix.sync.aligned.m8n8.x4.shared.b16 {%0,%1,%2,%3}, [%4];"
        : "=r"(r[0]), "=r"(r[1]), "=r"(r[2]), "=r"(r[3]) : "r"(addr));
}
// bf16 mma with fp32 accumulate (sm_80+ baseline PTX)
__device__ __forceinline__ void mma_bf16(float* d, const uint32_t* a,
                                         uint32_t b0, uint32_t b1) {
    asm volatile(
        "mma.sync.aligned.m16n8k16.row.col.f32.bf16.bf16.f32 "
        "{%0,%1,%2,%3}, {%4,%5,%6,%7}, {%8,%9}, {%0,%1,%2,%3};"
        : "+f"(d[0]), "+f"(d[1]), "+f"(d[2]), "+f"(d[3])
        : "r"(a[0]), "r"(a[1]), "r"(a[2]), "r"(a[3]), "r"(b0), "r"(b1));
}

// ---------------------------------------------------------------------------
// SMEM layout (bytes into dynamic smem)
//   A splits : 3 x [128 rows x 128B] = 49152
//   B splits : 3 x [256 rows x 128B] = 98304
//   (A+B region reused as hs[128][HS_STRIDE] f32 in the epilogue = 133120 B)
// ---------------------------------------------------------------------------
#define SA_OFF      0
#define SB_OFF      49152
#define W2S_OFF     147456     // float[2048]
#define BS1_OFF     155648     // float[256]
#define SCNT_OFF    156672     // int[8]  (expert reuses as sidx[128])
#define SBASE_OFF   157248
#define SROWS_OFF   157280     // int[1024]
#define SMEM_BYTES  161376
#define HS_STRIDE   260

// ---------------------------------------------------------------------------
// bf16 3-term split
// ---------------------------------------------------------------------------
__device__ __forceinline__ void split3(float v, __nv_bfloat16& h, __nv_bfloat16& m,
                                       __nv_bfloat16& l) {
    h = __float2bfloat16_rn(v);
    float r = v - __bfloat162float(h);
    m = __float2bfloat16_rn(r);
    float r2 = r - __bfloat162float(m);
    l = __float2bfloat16_rn(r2);
}
__device__ __forceinline__ uint32_t pack_bf(__nv_bfloat16 a, __nv_bfloat16 b) {
    return (uint32_t)__bfloat16_as_ushort(a) | ((uint32_t)__bfloat16_as_ushort(b) << 16);
}

// ---------------------------------------------------------------------------
// mma.sync mainloop: acc[128,256] += src[rows,256] @ Wt[256,256]^T
// 6-term bf16 split (hh,hm,mh,mm,hl,lh). K chunked by 64.
// Warp tile 32x64: warp_m = warp&3 (row group), warp_n = warp>>2 (col group).
// acc[mt][nt][4]: mt in {0,1} (16-row halves), nt in 0..7 (8-col tiles).
// ---------------------------------------------------------------------------
template <bool GATHER>
__device__ __forceinline__ void mma_mainloop(
    const float* __restrict__ src,
    const __nv_bfloat16* __restrict__ Bh, const __nv_bfloat16* __restrict__ Bm,
    const __nv_bfloat16* __restrict__ Bl,
    char* sm, uint32_t smem_base, const int* sidx, int row0,
    float (&acc)[2][8][4])
{
    const int tid  = threadIdx.x;
    const int lane = tid & 31;
    const int warp = tid >> 5;
    const int warp_m = warp & 3;
    const int warp_n = warp >> 2;

    char* A0 = sm + SA_OFF;
    char* A1 = sm + SA_OFF + 16384;
    char* A2 = sm + SA_OFF + 32768;
    char* B0 = sm + SB_OFF;
    char* B1 = sm + SB_OFF + 32768;
    char* B2 = sm + SB_OFF + 65536;
    const uint32_t aBase = smem_base + SA_OFF;
    const uint32_t bBase = smem_base + SB_OFF;

    // ldmatrix per-lane logical coordinates (element units within a tile)
    const uint32_t a_row   = warp_m * 32 + (lane & 15);   // + mt*16
    const uint32_t a_k8    = (lane >> 4) * 8;             // + ks*16
    const uint32_t b_row   = warp_n * 64 + ((lane >> 4) << 3) + (lane & 7);  // + nq*16
    const uint32_t b_k8    = ((lane >> 3) & 1) * 8;       // + ks*16

    for (int kb = 0; kb < 4; ++kb) {
        __syncthreads();  // prior chunk's compute done before overwrite

        // ---- stage A: 128 rows x 64 k fp32 -> 3 bf16 split tiles (SW128) ----
#pragma unroll
        for (int it = 0; it < 4; ++it) {
            int idx = it * 512 + tid;       // 0..2047
            int rl  = idx >> 4;             // row 0..127
            int kq  = idx & 15;             // float4 within 64 k
            int grow = GATHER ? sidx[rl] : (row0 + rl);
            float4 v = *(const float4*)(src + (size_t)grow * 256 + kb * 64 + kq * 4);
            __nv_bfloat16 h0, h1, h2, h3, m0, m1, m2, m3, l0, l1, l2, l3;
            split3(v.x, h0, m0, l0); split3(v.y, h1, m1, l1);
            split3(v.z, h2, m2, l2); split3(v.w, h3, m3, l3);
            uint32_t sw = SMEM_SWIZZLE_128B((uint32_t)(rl * 128 + kq * 8));
            *(uint2*)(A0 + sw) = make_uint2(pack_bf(h0, h1), pack_bf(h2, h3));
            *(uint2*)(A1 + sw) = make_uint2(pack_bf(m0, m1), pack_bf(m2, m3));
            *(uint2*)(A2 + sw) = make_uint2(pack_bf(l0, l1), pack_bf(l2, l3));
        }
        // ---- stage B: 256 rows x 64 k bf16, 3 splits (SW128) ----
#pragma unroll
        for (int it = 0; it < 4; ++it) {
            int idx = it * 512 + tid;       // 0..2047
            int n  = idx >> 3;              // row 0..255
            int kq = idx & 7;               // 8-bf16 (16B) chunk
            size_t goff = (size_t)n * 256 + kb * 64 + kq * 8;
            uint32_t sw = SMEM_SWIZZLE_128B((uint32_t)(n * 128 + kq * 16));
            *(uint4*)(B0 + sw) = *(const uint4*)(Bh + goff);
            *(uint4*)(B1 + sw) = *(const uint4*)(Bm + goff);
            *(uint4*)(B2 + sw) = *(const uint4*)(Bl + goff);
        }
        __syncthreads();

        // ---- compute: 6 split-product passes over this K chunk ----
#pragma unroll
        for (int p = 0; p < 6; ++p) {
            // pass -> (A split, B split): hh,hm,mh,mm,hl,lh
            const int pa = (p == 0 || p == 1 || p == 4) ? 0 : (p == 5 ? 2 : 1);
            const int pb = (p == 0 || p == 2 || p == 5) ? 0 : (p == 4 ? 2 : 1);
            const uint32_t ab = aBase + pa * 16384;
            const uint32_t bb = bBase + pb * 32768;
#pragma unroll
            for (int ks = 0; ks < 4; ++ks) {
                uint32_t a[2][4];
#pragma unroll
                for (int mt = 0; mt < 2; ++mt) {
                    uint32_t off = (a_row + mt * 16) * 128 + (ks * 16 + a_k8) * 2;
                    ldsm_x4(a[mt], ab + SMEM_SWIZZLE_128B(off));
                }
#pragma unroll
                for (int nq = 0; nq < 4; ++nq) {    // each x4 feeds 2 n8-tiles
                    uint32_t off = (b_row + nq * 16) * 128 + (ks * 16 + b_k8) * 2;
                    uint32_t r[4];
                    ldsm_x4(r, bb + SMEM_SWIZZLE_128B(off));
                    mma_bf16(acc[0][nq * 2],     a[0], r[0], r[1]);
                    mma_bf16(acc[1][nq * 2],     a[1], r[0], r[1]);
                    mma_bf16(acc[0][nq * 2 + 1], a[0], r[2], r[3]);
                    mma_bf16(acc[1][nq * 2 + 1], a[1], r[2], r[3]);
                }
            }
        }
    }
}

// acc -> bias+relu -> hs staging (reuses tile smem; caller syncs around it)
__device__ __forceinline__ void epilogue_stage_hs(char* sm, const float (&acc)[2][8][4],
                                                  const float* bs1) {
    const int tid = threadIdx.x, lane = tid & 31, warp = tid >> 5;
    const int warp_m = warp & 3, warp_n = warp >> 2;
    float* hs = (float*)sm;
    const int rbase = warp_m * 32 + (lane >> 2);
    const int cbase = warp_n * 64 + (lane & 3) * 2;
#pragma unroll
    for (int mt = 0; mt < 2; ++mt) {
#pragma unroll
        for (int nt = 0; nt < 8; ++nt) {
            const int cc = cbase + nt * 8;
            const float bias0 = bs1[cc], bias1 = bs1[cc + 1];
            const int r0 = rbase + mt * 16;
            hs[r0 * HS_STRIDE + cc]           = fmaxf(acc[mt][nt][0] + bias0, 0.f);
            hs[r0 * HS_STRIDE + cc + 1]       = fmaxf(acc[mt][nt][1] + bias1, 0.f);
            hs[(r0 + 8) * HS_STRIDE + cc]     = fmaxf(acc[mt][nt][2] + bias0, 0.f);
            hs[(r0 + 8) * HS_STRIDE + cc + 1] = fmaxf(acc[mt][nt][3] + bias1, 0.f);
        }
    }
}

// ---------------------------------------------------------------------------
// fp32 head helpers (proven)
// ---------------------------------------------------------------------------
__device__ __forceinline__ void partial_logits(const float* w2s, const float h[8],
                                               int c0, float p[8]) {
#pragma unroll
    for (int c = 0; c < 8; ++c) p[c] = 0.f;
#pragma unroll
    for (int j = 0; j < 8; ++j) {
        float4 wlo = *(const float4*)(w2s + (c0 + j) * 8);
        float4 whi = *(const float4*)(w2s + (c0 + j) * 8 + 4);
        p[0] += h[j] * wlo.x; p[1] += h[j] * wlo.y;
        p[2] += h[j] * wlo.z; p[3] += h[j] * wlo.w;
        p[4] += h[j] * whi.x; p[5] += h[j] * whi.y;
        p[6] += h[j] * whi.z; p[7] += h[j] * whi.w;
    }
}
__device__ __forceinline__ void butterfly_reduce8(float p[8]) {
#pragma unroll
    for (int off = 16; off > 0; off >>= 1) {
#pragma unroll
        for (int c = 0; c < 8; ++c)
            p[c] += __shfl_xor_sync(0xffffffffu, p[c], off);
    }
}

// ---------------------------------------------------------------------------
// Kernel: reset expert counters
// ---------------------------------------------------------------------------
__global__ void reset_kernel() {
    if (threadIdx.x < C_N) g_cnt[threadIdx.x] = 0;
}

// ---------------------------------------------------------------------------
// Kernel: transpose + 3-term bf16 split of W1 and Wc1[0..7] -> g_B{h,m,l}
// layout: [mat 0..8][n 0..255][k 0..255]  (K-major)
// ---------------------------------------------------------------------------
__global__ void prep_kernel(const float* __restrict__ W1, const float* __restrict__ Wc1) {
    int idx = blockIdx.x * 512 + threadIdx.x;
    if (idx >= 9 * 65536) return;
    int m   = idx >> 16;
    int rem = idx & 65535;
    int n = rem >> 8, k = rem & 255;
    float v = (m == 0) ? W1[k * 256 + n] : Wc1[(size_t)(m - 1) * 65536 + k * 256 + n];
    __nv_bfloat16 h, mm, l;
    split3(v, h, mm, l);
    g_Bh[idx] = h; g_Bm[idx] = mm; g_Bl[idx] = l;
}

// ---------------------------------------------------------------------------
// Kernel 1: root GEMM (mma.sync) + relu + head + softmax routing + bucketing
// ---------------------------------------------------------------------------
__global__ void __launch_bounds__(512, 1) root_kernel(
    const float* __restrict__ x, const float* __restrict__ b1,
    const float* __restrict__ W2, const float* __restrict__ b2,
    const float* __restrict__ tau,
    float* __restrict__ out_logits, float* __restrict__ out_h,
    float* __restrict__ out_depth)
{
    extern __shared__ char sm[];
    const uint32_t smem_base = smem_to_u32(sm);
    const int tid = threadIdx.x, lane = tid & 31, warp = tid >> 5;
    const int wr0 = warp * 8, c0 = lane * 8;
    const int row0 = blockIdx.x * 128;

    float* w2s = (float*)(sm + W2S_OFF);
    float* bs1 = (float*)(sm + BS1_OFF);
    int* scnt  = (int*)(sm + SCNT_OFF);
    int* sbase = (int*)(sm + SBASE_OFF);
    int* srows = (int*)(sm + SROWS_OFF);

    if (tid < 8) scnt[tid] = 0;
    *(float4*)(w2s + tid * 4) = *(const float4*)(W2 + tid * 4);
    if (tid < 64) *(float4*)(bs1 + tid * 4) = *(const float4*)(b1 + tid * 4);
    __syncthreads();

    float acc[2][8][4];
#pragma unroll
    for (int i = 0; i < 2; ++i)
#pragma unroll
        for (int j = 0; j < 8; ++j)
#pragma unroll
            for (int q = 0; q < 4; ++q) acc[i][j][q] = 0.f;

    mma_mainloop<false>(x, g_Bh, g_Bm, g_Bl, sm, smem_base, nullptr, row0, acc);

    __syncthreads();
    epilogue_stage_hs(sm, acc, bs1);
    __syncthreads();

    const float* hs = (const float*)sm;

    float b2r[8], taur[8];
    {
        float4 t0 = *(const float4*)(b2);  float4 t1 = *(const float4*)(b2 + 4);
        b2r[0] = t0.x; b2r[1] = t0.y; b2r[2] = t0.z; b2r[3] = t0.w;
        b2r[4] = t1.x; b2r[5] = t1.y; b2r[6] = t1.z; b2r[7] = t1.w;
        float4 u0 = *(const float4*)(tau); float4 u1 = *(const float4*)(tau + 4);
        taur[0] = u0.x; taur[1] = u0.y; taur[2] = u0.z; taur[3] = u0.w;
        taur[4] = u1.x; taur[5] = u1.y; taur[6] = u1.z; taur[7] = u1.w;
    }

#pragma unroll
    for (int i = 0; i < 8; ++i) {
        const int r = row0 + wr0 + i;
        const float* hr = hs + (size_t)(wr0 + i) * HS_STRIDE + c0;
        float h[8];
        {
            float4 t0 = *(const float4*)(hr);
            float4 t1 = *(const float4*)(hr + 4);
            h[0] = t0.x; h[1] = t0.y; h[2] = t0.z; h[3] = t0.w;
            h[4] = t1.x; h[5] = t1.y; h[6] = t1.z; h[7] = t1.w;
        }
        *(float4*)(out_h + (size_t)r * 256 + c0)     = make_float4(h[0], h[1], h[2], h[3]);
        *(float4*)(out_h + (size_t)r * 256 + c0 + 4) = make_float4(h[4], h[5], h[6], h[7]);

        float p[8];
        partial_logits(w2s, h, c0, p);
        butterfly_reduce8(p);

        if (lane == i) {
            float lg[8];
#pragma unroll
            for (int c = 0; c < 8; ++c) lg[c] = p[c] + b2r[c];
            float m = lg[0];
#pragma unroll
            for (int c = 1; c < 8; ++c) m = fmaxf(m, lg[c]);
            float e[8]; float s = 0.f;
#pragma unroll
            for (int c = 0; c < 8; ++c) { e[c] = expf(lg[c] - m); s += e[c]; }
            const float inv = 1.0f / s;
            int best = -1; float bv = -1.0f;
#pragma unroll
            for (int c = 0; c < 8; ++c) {
                float pr = e[c] * inv;
                if (pr >= taur[c] && pr > bv) { bv = pr; best = c; }
            }
            *(float4*)(out_logits + (size_t)r * 8)     = make_float4(lg[0], lg[1], lg[2], lg[3]);
            *(float4*)(out_logits + (size_t)r * 8 + 4) = make_float4(lg[4], lg[5], lg[6], lg[7]);
            out_depth[r] = (best >= 0) ? 1.0f : 0.0f;
            if (best >= 0) {
                int pos = atomicAdd(&scnt[best], 1);
                srows[best * 128 + pos] = r;
            }
        }
    }

    __syncthreads();
    if (tid < 8) sbase[tid] = atomicAdd(&g_cnt[tid], scnt[tid]);
    __syncthreads();
    for (int s2 = tid; s2 < 8 * 128; s2 += 512) {
        int e2 = s2 >> 7, i2 = s2 & 127;
        if (i2 < scnt[e2]) g_rows[e2 * B_N + sbase[e2] + i2] = srows[e2 * 128 + i2];
    }
}

// ---------------------------------------------------------------------------
// Kernel 2: per-expert gathered GEMM (mma.sync); overwrites routed rows
// ---------------------------------------------------------------------------
__global__ void __launch_bounds__(512, 1) expert_kernel(
    const float* __restrict__ bc1, const float* __restrict__ Wc2,
    const float* __restrict__ bc2,
    float* out_logits, float* out_h)
{
    const int c = blockIdx.y;
    const int cnt = g_cnt[c];
    const int start = blockIdx.x * 128;
    if (start >= cnt) return;
    const int n = min(128, cnt - start);

    extern __shared__ char sm[];
    const uint32_t smem_base = smem_to_u32(sm);
    const int tid = threadIdx.x, lane = tid & 31, warp = tid >> 5;
    const int wr0 = warp * 8, c0 = lane * 8;

    float* w2s = (float*)(sm + W2S_OFF);
    float* bs1 = (float*)(sm + BS1_OFF);
    int* sidx  = (int*)(sm + SCNT_OFF);     // 128 ints (root-only region reused)

    if (tid < 128) {
        int t = tid < n ? tid : (n - 1);    // tail pad with valid row (never stored)
        sidx[tid] = g_rows[c * B_N + start + t];
    }
    *(float4*)(w2s + tid * 4) = *(const float4*)(Wc2 + (size_t)c * 2048 + tid * 4);
    if (tid < 64) *(float4*)(bs1 + tid * 4) = *(const float4*)(bc1 + (size_t)c * 256 + tid * 4);
    __syncthreads();

    float acc[2][8][4];
#pragma unroll
    for (int i = 0; i < 2; ++i)
#pragma unroll
        for (int j = 0; j < 8; ++j)
#pragma unroll
            for (int q = 0; q < 4; ++q) acc[i][j][q] = 0.f;

    const size_t moff = (size_t)(1 + c) * 65536;
    mma_mainloop<true>(out_h, g_Bh + moff, g_Bm + moff, g_Bl + moff,
                       sm, smem_base, sidx, 0, acc);

    __syncthreads();
    epilogue_stage_hs(sm, acc, bs1);
    __syncthreads();

    const float* hs = (const float*)sm;

    float b2r[8];
    {
        float4 t0 = *(const float4*)(bc2 + c * 8);
        float4 t1 = *(const float4*)(bc2 + c * 8 + 4);
        b2r[0] = t0.x; b2r[1] = t0.y; b2r[2] = t0.z; b2r[3] = t0.w;
        b2r[4] = t1.x; b2r[5] = t1.y; b2r[6] = t1.z; b2r[7] = t1.w;
    }

#pragma unroll
    for (int i = 0; i < 8; ++i) {
        const bool valid = (wr0 + i) < n;
        const int r = sidx[wr0 + i];
        const float* hr = hs + (size_t)(wr0 + i) * HS_STRIDE + c0;
        float h[8];
        {
            float4 t0 = *(const float4*)(hr);
            float4 t1 = *(const float4*)(hr + 4);
            h[0] = t0.x; h[1] = t0.y; h[2] = t0.z; h[3] = t0.w;
            h[4] = t1.x; h[5] = t1.y; h[6] = t1.z; h[7] = t1.w;
        }
        if (valid) {
            *(float4*)(out_h + (size_t)r * 256 + c0)     = make_float4(h[0], h[1], h[2], h[3]);
            *(float4*)(out_h + (size_t)r * 256 + c0 + 4) = make_float4(h[4], h[5], h[6], h[7]);
        }
        float p[8];
        partial_logits(w2s, h, c0, p);
        butterfly_reduce8(p);
        if (lane == i && valid) {
            float lg[8];
#pragma unroll
            for (int cc = 0; cc < 8; ++cc) lg[cc] = p[cc] + b2r[cc];
            *(float4*)(out_logits + (size_t)r * 8)     = make_float4(lg[0], lg[1], lg[2], lg[3]);
            *(float4*)(out_logits + (size_t)r * 8 + 4) = make_float4(lg[4], lg[5], lg[6], lg[7]);
        }
    }
}

// ---------------------------------------------------------------------------
// Launcher (graph-capturable: kernel launches only)
// ---------------------------------------------------------------------------
extern "C" void kernel_launch(void* const* d_in, const int* in_sizes, int n_in,
                              void* d_out, int out_size)
{
    const float* x   = (const float*)d_in[0];
    const float* W1  = (const float*)d_in[1];
    const float* b1  = (const float*)d_in[2];
    const float* W2  = (const float*)d_in[3];
    const float* b2  = (const float*)d_in[4];
    const float* Wc1 = (const float*)d_in[5];
    const float* bc1 = (const float*)d_in[6];
    const float* Wc2 = (const float*)d_in[7];
    const float* bc2 = (const float*)d_in[8];
    const float* tau = (const float*)d_in[9];

    float* out        = (float*)d_out;
    float* out_logits = out;
    float* out_h      = out + (size_t)B_N * C_N;
    float* out_depth  = out + (size_t)B_N * C_N + (size_t)B_N * H_N;

    cudaFuncSetAttribute(root_kernel,   cudaFuncAttributeMaxDynamicSharedMemorySize, SMEM_BYTES);
    cudaFuncSetAttribute(expert_kernel, cudaFuncAttributeMaxDynamicSharedMemorySize, SMEM_BYTES);

    prep_kernel<<<(9 * 65536 + 511) / 512, 512>>>(W1, Wc1);
    reset_kernel<<<1, 32>>>();
    root_kernel<<<B_N / 128, 512, SMEM_BYTES>>>(
        x, b1, W2, b2, tau, out_logits, out_h, out_depth);
    expert_kernel<<<dim3(B_N / 128, C_N), 512, SMEM_BYTES>>>(
        bc1, Wc2, bc2, out_logits, out_h);
}

// round 16
// speedup vs baseline: 1.2199x; 1.2199x over previous
#include <cuda_runtime.h>
#include <cuda_bf16.h>
#include <cstdint>
#include <cstddef>

// Problem constants
#define B_N 131072
#define H_N 256
#define C_N 8

// ---------------------------------------------------------------------------
// Device globals (no allocations allowed)
// ---------------------------------------------------------------------------
__device__ int g_cnt[C_N];
__device__ int g_rows[C_N * B_N];
// Transposed bf16 3-term splits of [W1 ; Wc1[0..7]] as [9][N=256][K=256], K-major
__device__ __nv_bfloat16 g_Bh[9 * 65536];
__device__ __nv_bfloat16 g_Bm[9 * 65536];
__device__ __nv_bfloat16 g_Bl[9 * 65536];

// ---------------------------------------------------------------------------
// Helpers
// ---------------------------------------------------------------------------
__device__ __forceinline__ uint32_t smem_to_u32(const void* p) {
    uint32_t a;
    asm("{ .reg .u64 t; cvta.to.shared.u64 t, %1; cvt.u32.u64 %0, t; }" : "=r"(a) : "l"(p));
    return a;
}
#define SMEM_SWIZZLE_128B(o) ((o) ^ (((o) >> 3) & 0x70))

__device__ __forceinline__ void ldsm_x4(uint32_t* r, uint32_t addr) {
    asm volatile("ldmatrix.sync.aligned.m8n8.x4.shared.b16 {%0,%1,%2,%3}, [%4];"
        : "=r"(r[0]), "=r"(r[1]), "=r"(r[2]), "=r"(r[3]) : "r"(addr));
}
__device__ __forceinline__ void mma_bf16(float* d, const uint32_t* a,
                                         uint32_t b0, uint32_t b1) {
    asm volatile(
        "mma.sync.aligned.m16n8k16.row.col.f32.bf16.bf16.f32 "
        "{%0,%1,%2,%3}, {%4,%5,%6,%7}, {%8,%9}, {%0,%1,%2,%3};"
        : "+f"(d[0]), "+f"(d[1]), "+f"(d[2]), "+f"(d[3])
        : "r"(a[0]), "r"(a[1]), "r"(a[2]), "r"(a[3]), "r"(b0), "r"(b1));
}
// cp.async (sm_80 baseline PTX)
__device__ __forceinline__ void cp16(uint32_t dst, const void* src) {
    asm volatile("cp.async.cg.shared.global [%0], [%1], 16;" :: "r"(dst), "l"(src));
}
__device__ __forceinline__ void cp_commit() { asm volatile("cp.async.commit_group;" ::: "memory"); }
__device__ __forceinline__ void cp_wait0()  { asm volatile("cp.async.wait_group 0;" ::: "memory"); }

// ---------------------------------------------------------------------------
// SMEM layout (bytes)
//   ARAW : 2 x [128 rows x 64 f32]   = 65536   (cp.async raw A chunks)
//   ASP  : 3 x [128 rows x 128B]     = 49152   (A bf16 splits, rebuilt per chunk)
//   BSP  : 2 x [256 rows x 128B]     = 65536   (B split ping-pong)
//   (region 0..180224 reused as hs[128][HS_STRIDE] f32 = 133120 in epilogue)
// ---------------------------------------------------------------------------
#define ARAW_OFF   0
#define ASP_OFF    65536
#define BSP_OFF    114688
#define W2S_OFF    180224     // float[2048]
#define BS1_OFF    188416     // float[256]
#define SCNT_OFF   189440     // int[8]  (expert reuses as sidx[128])
#define SBASE_OFF  189472     // int[8]
#define SROWS_OFF  189504     // int[1024]
#define SMEM_BYTES 193664
#define HS_STRIDE  260

// ---------------------------------------------------------------------------
// bf16 3-term split
// ---------------------------------------------------------------------------
__device__ __forceinline__ void split3(float v, __nv_bfloat16& h, __nv_bfloat16& m,
                                       __nv_bfloat16& l) {
    h = __float2bfloat16_rn(v);
    float r = v - __bfloat162float(h);
    m = __float2bfloat16_rn(r);
    float r2 = r - __bfloat162float(m);
    l = __float2bfloat16_rn(r2);
}
__device__ __forceinline__ uint32_t pack_bf(__nv_bfloat16 a, __nv_bfloat16 b) {
    return (uint32_t)__bfloat16_as_ushort(a) | ((uint32_t)__bfloat16_as_ushort(b) << 16);
}

// ---------------------------------------------------------------------------
// Pipeline stages
// ---------------------------------------------------------------------------
// Raw A chunk: 128 rows x 64 f32, cp.async (2 x 16B per thread @ 1024 thr)
template <bool GATHER>
__device__ __forceinline__ void issue_A(const float* __restrict__ src, const int* sidx,
                                        int row0, int kb, uint32_t dstBase, int tid) {
#pragma unroll
    for (int it = 0; it < 2; ++it) {
        int idx = it * 1024 + tid;      // 0..2047
        int rl  = idx >> 4;             // row 0..127
        int kq  = idx & 15;             // 16B unit within 64 floats
        int grow = GATHER ? sidx[rl] : (row0 + rl);
        cp16(dstBase + rl * 256 + kq * 16,
             src + (size_t)grow * 256 + kb * 64 + kq * 4);
    }
}
// B split chunk: 256 rows x 64 bf16 -> SW128 (2 x 16B per thread)
__device__ __forceinline__ void issue_B(const __nv_bfloat16* __restrict__ Bsp, int kb,
                                        uint32_t dstBase, int tid) {
#pragma unroll
    for (int it = 0; it < 2; ++it) {
        int idx = it * 1024 + tid;      // 0..2047
        int n  = idx >> 3;              // row 0..255
        int kq = idx & 7;               // 16B unit
        cp16(dstBase + SMEM_SWIZZLE_128B((uint32_t)(n * 128 + kq * 16)),
             Bsp + (size_t)n * 256 + kb * 64 + kq * 8);
    }
}
// ARAW[pb] (f32) -> 3 bf16 split tiles in ASP (SW128)
__device__ __forceinline__ void convert_A(char* sm, uint32_t arawBase, int tid) {
    const float* Araw = (const float*)(sm + (arawBase));
    char* A0 = sm + ASP_OFF;
    char* A1 = sm + ASP_OFF + 16384;
    char* A2 = sm + ASP_OFF + 32768;
#pragma unroll
    for (int it = 0; it < 2; ++it) {
        int idx = it * 1024 + tid;
        int rl  = idx >> 4;
        int kq  = idx & 15;
        float4 v = *(const float4*)(Araw + rl * 64 + kq * 4);
        __nv_bfloat16 h0, h1, h2, h3, m0, m1, m2, m3, l0, l1, l2, l3;
        split3(v.x, h0, m0, l0); split3(v.y, h1, m1, l1);
        split3(v.z, h2, m2, l2); split3(v.w, h3, m3, l3);
        uint32_t sw = SMEM_SWIZZLE_128B((uint32_t)(rl * 128 + kq * 8));
        *(uint2*)(A0 + sw) = make_uint2(pack_bf(h0, h1), pack_bf(h2, h3));
        *(uint2*)(A1 + sw) = make_uint2(pack_bf(m0, m1), pack_bf(m2, m3));
        *(uint2*)(A2 + sw) = make_uint2(pack_bf(l0, l1), pack_bf(l2, l3));
    }
}

// Compute one stage: NA A-splits against the B split in bBase.
// Warp tile 32x32: warp_m = warp&3 (4 x 32 rows), warp_n = warp>>2 (8 x 32 cols).
template <int NA>
__device__ __forceinline__ void compute_stage(uint32_t aspBase, uint32_t bBase,
                                              float (&acc)[2][4][4],
                                              int lane, int warp_m, int warp_n) {
    const uint32_t a_row = warp_m * 32 + (lane & 15);
    const uint32_t a_k8  = (lane >> 4) * 8;
    const uint32_t b_row = warp_n * 32 + ((lane >> 4) << 3) + (lane & 7);
    const uint32_t b_k8  = ((lane >> 3) & 1) * 8;
#pragma unroll
    for (int ks = 0; ks < 4; ++ks) {
        uint32_t bfr[2][4];
#pragma unroll
        for (int nq = 0; nq < 2; ++nq)
            ldsm_x4(bfr[nq], bBase + SMEM_SWIZZLE_128B(
                (b_row + nq * 16) * 128 + (ks * 16 + b_k8) * 2));
#pragma unroll
        for (int a = 0; a < NA; ++a) {
            uint32_t af[2][4];
#pragma unroll
            for (int mt = 0; mt < 2; ++mt)
                ldsm_x4(af[mt], aspBase + a * 16384 + SMEM_SWIZZLE_128B(
                    (a_row + mt * 16) * 128 + (ks * 16 + a_k8) * 2));
#pragma unroll
            for (int mt = 0; mt < 2; ++mt) {
#pragma unroll
                for (int nq = 0; nq < 2; ++nq) {
                    mma_bf16(acc[mt][nq * 2],     af[mt], bfr[nq][0], bfr[nq][1]);
                    mma_bf16(acc[mt][nq * 2 + 1], af[mt], bfr[nq][2], bfr[nq][3]);
                }
            }
        }
    }
}

// ---------------------------------------------------------------------------
// Pipelined mainloop: acc[128,256] += src[rows,256] @ Wt^T, 6-term bf16 split.
// 12 stages = 4 K-chunks x 3 B-splits; B ping-pong + raw-A double buffer.
// ---------------------------------------------------------------------------
template <bool GATHER>
__device__ __forceinline__ void mma_pipeline(
    const float* __restrict__ src,
    const __nv_bfloat16* __restrict__ Bh, const __nv_bfloat16* __restrict__ Bm,
    const __nv_bfloat16* __restrict__ Bl,
    char* sm, uint32_t smb, const int* sidx, int row0, float (&acc)[2][4][4])
{
    const int tid = threadIdx.x, lane = tid & 31, warp = tid >> 5;
    const int warp_m = warp & 3, warp_n = warp >> 2;
    const __nv_bfloat16* Bp[3] = {Bh, Bm, Bl};

    // prologue: A chunk 0 + B split 0 chunk 0
    issue_A<GATHER>(src, sidx, row0, 0, smb + ARAW_OFF, tid);
    issue_B(Bp[0], 0, smb + BSP_OFF, tid);
    cp_commit();

    int i = 0;
    for (int kb = 0; kb < 4; ++kb) {
#pragma unroll
        for (int s = 0; s < 3; ++s, ++i) {
            cp_wait0();
            __syncthreads();
            if (s == 0) {
                convert_A(sm, ARAW_OFF + (uint32_t)(kb & 1) * 32768, tid);
                __syncthreads();
            }
            // issue loads for stage i+1 (into the buffer not used by stage i)
            if (i + 1 < 12) {
                int ns  = (s == 2) ? 0 : s + 1;
                int nkb = (s == 2) ? kb + 1 : kb;
                issue_B(Bp[ns], nkb, smb + BSP_OFF + (uint32_t)((i + 1) & 1) * 32768, tid);
                if (s == 0 && kb + 1 < 4)
                    issue_A<GATHER>(src, sidx, row0, kb + 1,
                                    smb + ARAW_OFF + (uint32_t)((kb + 1) & 1) * 32768, tid);
            }
            cp_commit();
            const uint32_t bb = smb + BSP_OFF + (uint32_t)(i & 1) * 32768;
            if (s == 0)      compute_stage<3>(smb + ASP_OFF, bb, acc, lane, warp_m, warp_n);
            else if (s == 1) compute_stage<2>(smb + ASP_OFF, bb, acc, lane, warp_m, warp_n);
            else             compute_stage<1>(smb + ASP_OFF, bb, acc, lane, warp_m, warp_n);
        }
    }
}

// acc -> bias+relu -> hs staging (warp tile 32x32); caller syncs around it
__device__ __forceinline__ void epilogue_stage_hs(char* sm, const float (&acc)[2][4][4],
                                                  const float* bs1) {
    const int tid = threadIdx.x, lane = tid & 31, warp = tid >> 5;
    const int warp_m = warp & 3, warp_n = warp >> 2;
    float* hs = (float*)sm;
    const int rbase = warp_m * 32 + (lane >> 2);
    const int cbase = warp_n * 32 + (lane & 3) * 2;
#pragma unroll
    for (int mt = 0; mt < 2; ++mt) {
#pragma unroll
        for (int nt = 0; nt < 4; ++nt) {
            const int cc = cbase + nt * 8;
            const float bias0 = bs1[cc], bias1 = bs1[cc + 1];
            const int r0 = rbase + mt * 16;
            hs[r0 * HS_STRIDE + cc]           = fmaxf(acc[mt][nt][0] + bias0, 0.f);
            hs[r0 * HS_STRIDE + cc + 1]       = fmaxf(acc[mt][nt][1] + bias1, 0.f);
            hs[(r0 + 8) * HS_STRIDE + cc]     = fmaxf(acc[mt][nt][2] + bias0, 0.f);
            hs[(r0 + 8) * HS_STRIDE + cc + 1] = fmaxf(acc[mt][nt][3] + bias1, 0.f);
        }
    }
}

// ---------------------------------------------------------------------------
// fp32 head helpers (proven)
// ---------------------------------------------------------------------------
__device__ __forceinline__ void partial_logits(const float* w2s, const float h[8],
                                               int c0, float p[8]) {
#pragma unroll
    for (int c = 0; c < 8; ++c) p[c] = 0.f;
#pragma unroll
    for (int j = 0; j < 8; ++j) {
        float4 wlo = *(const float4*)(w2s + (c0 + j) * 8);
        float4 whi = *(const float4*)(w2s + (c0 + j) * 8 + 4);
        p[0] += h[j] * wlo.x; p[1] += h[j] * wlo.y;
        p[2] += h[j] * wlo.z; p[3] += h[j] * wlo.w;
        p[4] += h[j] * whi.x; p[5] += h[j] * whi.y;
        p[6] += h[j] * whi.z; p[7] += h[j] * whi.w;
    }
}
__device__ __forceinline__ void butterfly_reduce8(float p[8]) {
#pragma unroll
    for (int off = 16; off > 0; off >>= 1) {
#pragma unroll
        for (int c = 0; c < 8; ++c)
            p[c] += __shfl_xor_sync(0xffffffffu, p[c], off);
    }
}

// ---------------------------------------------------------------------------
// Kernel: reset expert counters
// ---------------------------------------------------------------------------
__global__ void reset_kernel() {
    if (threadIdx.x < C_N) g_cnt[threadIdx.x] = 0;
}

// ---------------------------------------------------------------------------
// Kernel: transpose + 3-term bf16 split of W1 and Wc1[0..7] -> g_B{h,m,l}
// ---------------------------------------------------------------------------
__global__ void prep_kernel(const float* __restrict__ W1, const float* __restrict__ Wc1) {
    int idx = blockIdx.x * 512 + threadIdx.x;
    if (idx >= 9 * 65536) return;
    int m   = idx >> 16;
    int rem = idx & 65535;
    int n = rem >> 8, k = rem & 255;
    float v = (m == 0) ? W1[k * 256 + n] : Wc1[(size_t)(m - 1) * 65536 + k * 256 + n];
    __nv_bfloat16 h, mm, l;
    split3(v, h, mm, l);
    g_Bh[idx] = h; g_Bm[idx] = mm; g_Bl[idx] = l;
}

// ---------------------------------------------------------------------------
// Kernel 1: root GEMM (pipelined mma.sync) + relu + head + routing + buckets
// ---------------------------------------------------------------------------
__global__ void __launch_bounds__(1024, 1) root_kernel(
    const float* __restrict__ x, const float* __restrict__ b1,
    const float* __restrict__ W2, const float* __restrict__ b2,
    const float* __restrict__ tau,
    float* __restrict__ out_logits, float* __restrict__ out_h,
    float* __restrict__ out_depth)
{
    extern __shared__ char sm[];
    const uint32_t smb = smem_to_u32(sm);
    const int tid = threadIdx.x, lane = tid & 31, warp = tid >> 5;
    const int c0 = lane * 8;
    const int row0 = blockIdx.x * 128;

    float* w2s = (float*)(sm + W2S_OFF);
    float* bs1 = (float*)(sm + BS1_OFF);
    int* scnt  = (int*)(sm + SCNT_OFF);
    int* sbase = (int*)(sm + SBASE_OFF);
    int* srows = (int*)(sm + SROWS_OFF);

    if (tid < 8) scnt[tid] = 0;
    if (tid < 512) *(float4*)(w2s + tid * 4) = *(const float4*)(W2 + tid * 4);
    if (tid < 64)  *(float4*)(bs1 + tid * 4) = *(const float4*)(b1 + tid * 4);
    __syncthreads();

    float acc[2][4][4];
#pragma unroll
    for (int i = 0; i < 2; ++i)
#pragma unroll
        for (int j = 0; j < 4; ++j)
#pragma unroll
            for (int q = 0; q < 4; ++q) acc[i][j][q] = 0.f;

    mma_pipeline<false>(x, g_Bh, g_Bm, g_Bl, sm, smb, nullptr, row0, acc);

    __syncthreads();
    epilogue_stage_hs(sm, acc, bs1);
    __syncthreads();

    const float* hs = (const float*)sm;

    float b2r[8], taur[8];
    {
        float4 t0 = *(const float4*)(b2);  float4 t1 = *(const float4*)(b2 + 4);
        b2r[0] = t0.x; b2r[1] = t0.y; b2r[2] = t0.z; b2r[3] = t0.w;
        b2r[4] = t1.x; b2r[5] = t1.y; b2r[6] = t1.z; b2r[7] = t1.w;
        float4 u0 = *(const float4*)(tau); float4 u1 = *(const float4*)(tau + 4);
        taur[0] = u0.x; taur[1] = u0.y; taur[2] = u0.z; taur[3] = u0.w;
        taur[4] = u1.x; taur[5] = u1.y; taur[6] = u1.z; taur[7] = u1.w;
    }

    // 32 warps x 4 rows each
#pragma unroll
    for (int i = 0; i < 4; ++i) {
        const int lr = warp * 4 + i;
        const int r  = row0 + lr;
        const float* hr = hs + (size_t)lr * HS_STRIDE + c0;
        float h[8];
        {
            float4 t0 = *(const float4*)(hr);
            float4 t1 = *(const float4*)(hr + 4);
            h[0] = t0.x; h[1] = t0.y; h[2] = t0.z; h[3] = t0.w;
            h[4] = t1.x; h[5] = t1.y; h[6] = t1.z; h[7] = t1.w;
        }
        *(float4*)(out_h + (size_t)r * 256 + c0)     = make_float4(h[0], h[1], h[2], h[3]);
        *(float4*)(out_h + (size_t)r * 256 + c0 + 4) = make_float4(h[4], h[5], h[6], h[7]);

        float p[8];
        partial_logits(w2s, h, c0, p);
        butterfly_reduce8(p);

        if (lane == i) {
            float lg[8];
#pragma unroll
            for (int c = 0; c < 8; ++c) lg[c] = p[c] + b2r[c];
            float m = lg[0];
#pragma unroll
            for (int c = 1; c < 8; ++c) m = fmaxf(m, lg[c]);
            float e[8]; float s = 0.f;
#pragma unroll
            for (int c = 0; c < 8; ++c) { e[c] = expf(lg[c] - m); s += e[c]; }
            const float inv = 1.0f / s;
            int best = -1; float bv = -1.0f;
#pragma unroll
            for (int c = 0; c < 8; ++c) {
                float pr = e[c] * inv;
                if (pr >= taur[c] && pr > bv) { bv = pr; best = c; }
            }
            *(float4*)(out_logits + (size_t)r * 8)     = make_float4(lg[0], lg[1], lg[2], lg[3]);
            *(float4*)(out_logits + (size_t)r * 8 + 4) = make_float4(lg[4], lg[5], lg[6], lg[7]);
            out_depth[r] = (best >= 0) ? 1.0f : 0.0f;
            if (best >= 0) {
                int pos = atomicAdd(&scnt[best], 1);
                srows[best * 128 + pos] = r;
            }
        }
    }

    __syncthreads();
    if (tid < 8) sbase[tid] = atomicAdd(&g_cnt[tid], scnt[tid]);
    __syncthreads();
    if (tid < 8 * 128) {
        int e2 = tid >> 7, i2 = tid & 127;
        if (i2 < scnt[e2]) g_rows[e2 * B_N + sbase[e2] + i2] = srows[e2 * 128 + i2];
    }
}

// ---------------------------------------------------------------------------
// Kernel 2: per-expert gathered GEMM (pipelined); overwrites routed rows
// ---------------------------------------------------------------------------
__global__ void __launch_bounds__(1024, 1) expert_kernel(
    const float* __restrict__ bc1, const float* __restrict__ Wc2,
    const float* __restrict__ bc2,
    float* out_logits, float* out_h)
{
    const int c = blockIdx.y;
    const int cnt = g_cnt[c];
    const int start = blockIdx.x * 128;
    if (start >= cnt) return;
    const int n = min(128, cnt - start);

    extern __shared__ char sm[];
    const uint32_t smb = smem_to_u32(sm);
    const int tid = threadIdx.x, lane = tid & 31, warp = tid >> 5;
    const int c0 = lane * 8;

    float* w2s = (float*)(sm + W2S_OFF);
    float* bs1 = (float*)(sm + BS1_OFF);
    int* sidx  = (int*)(sm + SCNT_OFF);

    if (tid < 128) {
        int t = tid < n ? tid : (n - 1);    // tail pad with valid row (never stored)
        sidx[tid] = g_rows[c * B_N + start + t];
    }
    if (tid < 512) *(float4*)(w2s + tid * 4) = *(const float4*)(Wc2 + (size_t)c * 2048 + tid * 4);
    if (tid < 64)  *(float4*)(bs1 + tid * 4) = *(const float4*)(bc1 + (size_t)c * 256 + tid * 4);
    __syncthreads();

    float acc[2][4][4];
#pragma unroll
    for (int i = 0; i < 2; ++i)
#pragma unroll
        for (int j = 0; j < 4; ++j)
#pragma unroll
            for (int q = 0; q < 4; ++q) acc[i][j][q] = 0.f;

    const size_t moff = (size_t)(1 + c) * 65536;
    mma_pipeline<true>(out_h, g_Bh + moff, g_Bm + moff, g_Bl + moff,
                       sm, smb, sidx, 0, acc);

    __syncthreads();
    epilogue_stage_hs(sm, acc, bs1);
    __syncthreads();

    const float* hs = (const float*)sm;

    float b2r[8];
    {
        float4 t0 = *(const float4*)(bc2 + c * 8);
        float4 t1 = *(const float4*)(bc2 + c * 8 + 4);
        b2r[0] = t0.x; b2r[1] = t0.y; b2r[2] = t0.z; b2r[3] = t0.w;
        b2r[4] = t1.x; b2r[5] = t1.y; b2r[6] = t1.z; b2r[7] = t1.w;
    }

#pragma unroll
    for (int i = 0; i < 4; ++i) {
        const int lr = warp * 4 + i;
        const bool valid = lr < n;
        const int r = sidx[lr];
        const float* hr = hs + (size_t)lr * HS_STRIDE + c0;
        float h[8];
        {
            float4 t0 = *(const float4*)(hr);
            float4 t1 = *(const float4*)(hr + 4);
            h[0] = t0.x; h[1] = t0.y; h[2] = t0.z; h[3] = t0.w;
            h[4] = t1.x; h[5] = t1.y; h[6] = t1.z; h[7] = t1.w;
        }
        if (valid) {
            *(float4*)(out_h + (size_t)r * 256 + c0)     = make_float4(h[0], h[1], h[2], h[3]);
            *(float4*)(out_h + (size_t)r * 256 + c0 + 4) = make_float4(h[4], h[5], h[6], h[7]);
        }
        float p[8];
        partial_logits(w2s, h, c0, p);
        butterfly_reduce8(p);
        if (lane == i && valid) {
            float lg[8];
#pragma unroll
            for (int cc = 0; cc < 8; ++cc) lg[cc] = p[cc] + b2r[cc];
            *(float4*)(out_logits + (size_t)r * 8)     = make_float4(lg[0], lg[1], lg[2], lg[3]);
            *(float4*)(out_logits + (size_t)r * 8 + 4) = make_float4(lg[4], lg[5], lg[6], lg[7]);
        }
    }
}

// ---------------------------------------------------------------------------
// Launcher (graph-capturable: kernel launches only)
// ---------------------------------------------------------------------------
extern "C" void kernel_launch(void* const* d_in, const int* in_sizes, int n_in,
                              void* d_out, int out_size)
{
    const float* x   = (const float*)d_in[0];
    const float* W1  = (const float*)d_in[1];
    const float* b1  = (const float*)d_in[2];
    const float* W2  = (const float*)d_in[3];
    const float* b2  = (const float*)d_in[4];
    const float* Wc1 = (const float*)d_in[5];
    const float* bc1 = (const float*)d_in[6];
    const float* Wc2 = (const float*)d_in[7];
    const float* bc2 = (const float*)d_in[8];
    const float* tau = (const float*)d_in[9];

    float* out        = (float*)d_out;
    float* out_logits = out;
    float* out_h      = out + (size_t)B_N * C_N;
    float* out_depth  = out + (size_t)B_N * C_N + (size_t)B_N * H_N;

    cudaFuncSetAttribute(root_kernel,   cudaFuncAttributeMaxDynamicSharedMemorySize, SMEM_BYTES);
    cudaFuncSetAttribute(expert_kernel, cudaFuncAttributeMaxDynamicSharedMemorySize, SMEM_BYTES);

    prep_kernel<<<(9 * 65536 + 511) / 512, 512>>>(W1, Wc1);
    reset_kernel<<<1, 32>>>();
    root_kernel<<<B_N / 128, 1024, SMEM_BYTES>>>(
        x, b1, W2, b2, tau, out_logits, out_h, out_depth);
    expert_kernel<<<dim3(B_N / 128, C_N), 1024, SMEM_BYTES>>>(
        bc1, Wc2, bc2, out_logits, out_h);
}

// round 17
// speedup vs baseline: 1.6656x; 1.3654x over previous
#include <cuda_runtime.h>
#include <cuda_fp16.h>
#include <cstdint>
#include <cstddef>

// Problem constants
#define B_N 131072
#define H_N 256
#define C_N 8

// ---------------------------------------------------------------------------
// Device globals (no allocations allowed)
// ---------------------------------------------------------------------------
__device__ int g_cnt[C_N];
__device__ int g_rows[C_N * B_N];
// Transposed fp16 2-term splits of [W1 ; Wc1[0..7]] as [9][N=256][K=256], K-major
__device__ __half g_Bh[9 * 65536];
__device__ __half g_Bl[9 * 65536];

// ---------------------------------------------------------------------------
// Helpers
// ---------------------------------------------------------------------------
__device__ __forceinline__ uint32_t smem_to_u32(const void* p) {
    uint32_t a;
    asm("{ .reg .u64 t; cvta.to.shared.u64 t, %1; cvt.u32.u64 %0, t; }" : "=r"(a) : "l"(p));
    return a;
}
#define SMEM_SWIZZLE_128B(o) ((o) ^ (((o) >> 3) & 0x70))

__device__ __forceinline__ void ldsm_x4(uint32_t* r, uint32_t addr) {
    asm volatile("ldmatrix.sync.aligned.m8n8.x4.shared.b16 {%0,%1,%2,%3}, [%4];"
        : "=r"(r[0]), "=r"(r[1]), "=r"(r[2]), "=r"(r[3]) : "r"(addr));
}
// fp16 mma with fp32 accumulate (sm_80 baseline PTX — survives non-'a' targets)
__device__ __forceinline__ void mma_fp16(float* d, const uint32_t* a,
                                         uint32_t b0, uint32_t b1) {
    asm volatile(
        "mma.sync.aligned.m16n8k16.row.col.f32.f16.f16.f32 "
        "{%0,%1,%2,%3}, {%4,%5,%6,%7}, {%8,%9}, {%0,%1,%2,%3};"
        : "+f"(d[0]), "+f"(d[1]), "+f"(d[2]), "+f"(d[3])
        : "r"(a[0]), "r"(a[1]), "r"(a[2]), "r"(a[3]), "r"(b0), "r"(b1));
}
// cp.async (sm_80 baseline PTX)
__device__ __forceinline__ void cp16(uint32_t dst, const void* src) {
    asm volatile("cp.async.cg.shared.global [%0], [%1], 16;" :: "r"(dst), "l"(src));
}
__device__ __forceinline__ void cp_commit() { asm volatile("cp.async.commit_group;" ::: "memory"); }
__device__ __forceinline__ void cp_wait0()  { asm volatile("cp.async.wait_group 0;" ::: "memory"); }

// ---------------------------------------------------------------------------
// SMEM layout (bytes)
//   ARAW : 2 x [128 rows x 64 f32]  = 65536  (cp.async raw A chunks, ping-pong)
//   ASP  : 2 x [128 rows x 128B]    = 32768  (A fp16 splits, rebuilt per chunk)
//   BSP  : 2 x [256 rows x 128B]    = 65536  (B split ping-pong)
//   (region 0..163840 reused as hs[128][HS_STRIDE] f32 = 133120 in epilogue)
// ---------------------------------------------------------------------------
#define ARAW_OFF   0
#define ASP_OFF    65536
#define BSP_OFF    98304
#define W2S_OFF    163840     // float[2048]
#define BS1_OFF    172032     // float[256]
#define SCNT_OFF   173056     // int[8]  (expert reuses as sidx[128])
#define SBASE_OFF  173088     // int[8]
#define SROWS_OFF  173120     // int[1024]
#define SMEM_BYTES 177216
#define HS_STRIDE  260

// ---------------------------------------------------------------------------
// fp16 2-term split: v = h + l + delta, |delta| <= 2^-24 |v|
// ---------------------------------------------------------------------------
__device__ __forceinline__ void split2(float v, __half& h, __half& l) {
    h = __float2half_rn(v);
    l = __float2half_rn(v - __half2float(h));
}
__device__ __forceinline__ uint32_t pack_h(__half a, __half b) {
    return (uint32_t)__half_as_ushort(a) | ((uint32_t)__half_as_ushort(b) << 16);
}

// ---------------------------------------------------------------------------
// Pipeline stages
// ---------------------------------------------------------------------------
// Raw A chunk: 128 rows x 64 f32, cp.async (2 x 16B per thread @ 1024 thr)
template <bool GATHER>
__device__ __forceinline__ void issue_A(const float* __restrict__ src, const int* sidx,
                                        int row0, int kb, uint32_t dstBase, int tid) {
#pragma unroll
    for (int it = 0; it < 2; ++it) {
        int idx = it * 1024 + tid;      // 0..2047
        int rl  = idx >> 4;             // row 0..127
        int kq  = idx & 15;             // 16B unit within 64 floats
        int grow = GATHER ? sidx[rl] : (row0 + rl);
        cp16(dstBase + rl * 256 + kq * 16,
             src + (size_t)grow * 256 + kb * 64 + kq * 4);
    }
}
// B split chunk: 256 rows x 64 fp16 -> SW128 (2 x 16B per thread)
__device__ __forceinline__ void issue_B(const __half* __restrict__ Bsp, int kb,
                                        uint32_t dstBase, int tid) {
#pragma unroll
    for (int it = 0; it < 2; ++it) {
        int idx = it * 1024 + tid;      // 0..2047
        int n  = idx >> 3;              // row 0..255
        int kq = idx & 7;               // 16B unit
        cp16(dstBase + SMEM_SWIZZLE_128B((uint32_t)(n * 128 + kq * 16)),
             Bsp + (size_t)n * 256 + kb * 64 + kq * 8);
    }
}
// ARAW (f32) -> 2 fp16 split tiles in ASP (SW128)
__device__ __forceinline__ void convert_A(char* sm, uint32_t arawBase, int tid) {
    const float* Araw = (const float*)(sm + arawBase);
    char* A0 = sm + ASP_OFF;
    char* A1 = sm + ASP_OFF + 16384;
#pragma unroll
    for (int it = 0; it < 2; ++it) {
        int idx = it * 1024 + tid;
        int rl  = idx >> 4;
        int kq  = idx & 15;
        float4 v = *(const float4*)(Araw + rl * 64 + kq * 4);
        __half h0, h1, h2, h3, l0, l1, l2, l3;
        split2(v.x, h0, l0); split2(v.y, h1, l1);
        split2(v.z, h2, l2); split2(v.w, h3, l3);
        uint32_t sw = SMEM_SWIZZLE_128B((uint32_t)(rl * 128 + kq * 8));
        *(uint2*)(A0 + sw) = make_uint2(pack_h(h0, h1), pack_h(h2, h3));
        *(uint2*)(A1 + sw) = make_uint2(pack_h(l0, l1), pack_h(l2, l3));
    }
}

// Compute one stage: NA A-splits (0..NA-1) against the B split in bBase.
// Warp tile 32x32: warp_m = warp&3 (4 x 32 rows), warp_n = warp>>2 (8 x 32 cols).
template <int NA>
__device__ __forceinline__ void compute_stage(uint32_t aspBase, uint32_t bBase,
                                              float (&acc)[2][4][4],
                                              int lane, int warp_m, int warp_n) {
    const uint32_t a_row = warp_m * 32 + (lane & 15);
    const uint32_t a_k8  = (lane >> 4) * 8;
    const uint32_t b_row = warp_n * 32 + ((lane >> 4) << 3) + (lane & 7);
    const uint32_t b_k8  = ((lane >> 3) & 1) * 8;
#pragma unroll
    for (int ks = 0; ks < 4; ++ks) {
        uint32_t bfr[2][4];
#pragma unroll
        for (int nq = 0; nq < 2; ++nq)
            ldsm_x4(bfr[nq], bBase + SMEM_SWIZZLE_128B(
                (b_row + nq * 16) * 128 + (ks * 16 + b_k8) * 2));
#pragma unroll
        for (int a = 0; a < NA; ++a) {
            uint32_t af[2][4];
#pragma unroll
            for (int mt = 0; mt < 2; ++mt)
                ldsm_x4(af[mt], aspBase + a * 16384 + SMEM_SWIZZLE_128B(
                    (a_row + mt * 16) * 128 + (ks * 16 + a_k8) * 2));
#pragma unroll
            for (int mt = 0; mt < 2; ++mt) {
#pragma unroll
                for (int nq = 0; nq < 2; ++nq) {
                    mma_fp16(acc[mt][nq * 2],     af[mt], bfr[nq][0], bfr[nq][1]);
                    mma_fp16(acc[mt][nq * 2 + 1], af[mt], bfr[nq][2], bfr[nq][3]);
                }
            }
        }
    }
}

// ---------------------------------------------------------------------------
// Pipelined mainloop: acc[128,256] += src[rows,256] @ Wt^T, fp16 2-split x
// 3 passes (hh, lh, hl). 8 stages = 4 K-chunks x 2 B-splits; ping-pong bufs.
// Stage s=0 (B=h): A splits {h,l}; stage s=1 (B=l): A split {h}.
// ---------------------------------------------------------------------------
template <bool GATHER>
__device__ __forceinline__ void mma_pipeline(
    const float* __restrict__ src,
    const __half* __restrict__ Bh, const __half* __restrict__ Bl,
    char* sm, uint32_t smb, const int* sidx, int row0, float (&acc)[2][4][4])
{
    const int tid = threadIdx.x, lane = tid & 31, warp = tid >> 5;
    const int warp_m = warp & 3, warp_n = warp >> 2;
    const __half* Bp[2] = {Bh, Bl};

    // prologue: A chunk 0 + B split h chunk 0
    issue_A<GATHER>(src, sidx, row0, 0, smb + ARAW_OFF, tid);
    issue_B(Bp[0], 0, smb + BSP_OFF, tid);
    cp_commit();

    int i = 0;
    for (int kb = 0; kb < 4; ++kb) {
#pragma unroll
        for (int s = 0; s < 2; ++s, ++i) {
            cp_wait0();
            __syncthreads();
            if (s == 0) {
                convert_A(sm, ARAW_OFF + (uint32_t)(kb & 1) * 32768, tid);
                __syncthreads();
            }
            // issue loads for stage i+1 (into the buffer not used by stage i)
            if (i + 1 < 8) {
                int ns  = (s == 1) ? 0 : 1;
                int nkb = (s == 1) ? kb + 1 : kb;
                issue_B(Bp[ns], nkb, smb + BSP_OFF + (uint32_t)((i + 1) & 1) * 32768, tid);
                if (s == 0 && kb + 1 < 4)
                    issue_A<GATHER>(src, sidx, row0, kb + 1,
                                    smb + ARAW_OFF + (uint32_t)((kb + 1) & 1) * 32768, tid);
            }
            cp_commit();
            const uint32_t bb = smb + BSP_OFF + (uint32_t)(i & 1) * 32768;
            if (s == 0) compute_stage<2>(smb + ASP_OFF, bb, acc, lane, warp_m, warp_n);
            else        compute_stage<1>(smb + ASP_OFF, bb, acc, lane, warp_m, warp_n);
        }
    }
}

// acc -> bias+relu -> hs staging (warp tile 32x32); caller syncs around it
__device__ __forceinline__ void epilogue_stage_hs(char* sm, const float (&acc)[2][4][4],
                                                  const float* bs1) {
    const int tid = threadIdx.x, lane = tid & 31, warp = tid >> 5;
    const int warp_m = warp & 3, warp_n = warp >> 2;
    float* hs = (float*)sm;
    const int rbase = warp_m * 32 + (lane >> 2);
    const int cbase = warp_n * 32 + (lane & 3) * 2;
#pragma unroll
    for (int mt = 0; mt < 2; ++mt) {
#pragma unroll
        for (int nt = 0; nt < 4; ++nt) {
            const int cc = cbase + nt * 8;
            const float bias0 = bs1[cc], bias1 = bs1[cc + 1];
            const int r0 = rbase + mt * 16;
            hs[r0 * HS_STRIDE + cc]           = fmaxf(acc[mt][nt][0] + bias0, 0.f);
            hs[r0 * HS_STRIDE + cc + 1]       = fmaxf(acc[mt][nt][1] + bias1, 0.f);
            hs[(r0 + 8) * HS_STRIDE + cc]     = fmaxf(acc[mt][nt][2] + bias0, 0.f);
            hs[(r0 + 8) * HS_STRIDE + cc + 1] = fmaxf(acc[mt][nt][3] + bias1, 0.f);
        }
    }
}

// ---------------------------------------------------------------------------
// fp32 head helpers (proven)
// ---------------------------------------------------------------------------
__device__ __forceinline__ void partial_logits(const float* w2s, const float h[8],
                                               int c0, float p[8]) {
#pragma unroll
    for (int c = 0; c < 8; ++c) p[c] = 0.f;
#pragma unroll
    for (int j = 0; j < 8; ++j) {
        float4 wlo = *(const float4*)(w2s + (c0 + j) * 8);
        float4 whi = *(const float4*)(w2s + (c0 + j) * 8 + 4);
        p[0] += h[j] * wlo.x; p[1] += h[j] * wlo.y;
        p[2] += h[j] * wlo.z; p[3] += h[j] * wlo.w;
        p[4] += h[j] * whi.x; p[5] += h[j] * whi.y;
        p[6] += h[j] * whi.z; p[7] += h[j] * whi.w;
    }
}
__device__ __forceinline__ void butterfly_reduce8(float p[8]) {
#pragma unroll
    for (int off = 16; off > 0; off >>= 1) {
#pragma unroll
        for (int c = 0; c < 8; ++c)
            p[c] += __shfl_xor_sync(0xffffffffu, p[c], off);
    }
}

// ---------------------------------------------------------------------------
// Kernel: reset expert counters
// ---------------------------------------------------------------------------
__global__ void reset_kernel() {
    if (threadIdx.x < C_N) g_cnt[threadIdx.x] = 0;
}

// ---------------------------------------------------------------------------
// Kernel: transpose + fp16 2-term split of W1 and Wc1[0..7] -> g_B{h,l}
// layout: [mat 0..8][n 0..255][k 0..255]  (K-major)
// ---------------------------------------------------------------------------
__global__ void prep_kernel(const float* __restrict__ W1, const float* __restrict__ Wc1) {
    int idx = blockIdx.x * 512 + threadIdx.x;
    if (idx >= 9 * 65536) return;
    int m   = idx >> 16;
    int rem = idx & 65535;
    int n = rem >> 8, k = rem & 255;
    float v = (m == 0) ? W1[k * 256 + n] : Wc1[(size_t)(m - 1) * 65536 + k * 256 + n];
    __half h, l;
    split2(v, h, l);
    g_Bh[idx] = h; g_Bl[idx] = l;
}

// ---------------------------------------------------------------------------
// Kernel 1: root GEMM (pipelined mma.sync) + relu + head + routing + buckets
// ---------------------------------------------------------------------------
__global__ void __launch_bounds__(1024, 1) root_kernel(
    const float* __restrict__ x, const float* __restrict__ b1,
    const float* __restrict__ W2, const float* __restrict__ b2,
    const float* __restrict__ tau,
    float* __restrict__ out_logits, float* __restrict__ out_h,
    float* __restrict__ out_depth)
{
    extern __shared__ char sm[];
    const uint32_t smb = smem_to_u32(sm);
    const int tid = threadIdx.x, lane = tid & 31, warp = tid >> 5;
    const int c0 = lane * 8;
    const int row0 = blockIdx.x * 128;

    float* w2s = (float*)(sm + W2S_OFF);
    float* bs1 = (float*)(sm + BS1_OFF);
    int* scnt  = (int*)(sm + SCNT_OFF);
    int* sbase = (int*)(sm + SBASE_OFF);
    int* srows = (int*)(sm + SROWS_OFF);

    if (tid < 8) scnt[tid] = 0;
    if (tid < 512) *(float4*)(w2s + tid * 4) = *(const float4*)(W2 + tid * 4);
    if (tid < 64)  *(float4*)(bs1 + tid * 4) = *(const float4*)(b1 + tid * 4);
    __syncthreads();

    float acc[2][4][4];
#pragma unroll
    for (int i = 0; i < 2; ++i)
#pragma unroll
        for (int j = 0; j < 4; ++j)
#pragma unroll
            for (int q = 0; q < 4; ++q) acc[i][j][q] = 0.f;

    mma_pipeline<false>(x, g_Bh, g_Bl, sm, smb, nullptr, row0, acc);

    __syncthreads();
    epilogue_stage_hs(sm, acc, bs1);
    __syncthreads();

    const float* hs = (const float*)sm;

    float b2r[8], taur[8];
    {
        float4 t0 = *(const float4*)(b2);  float4 t1 = *(const float4*)(b2 + 4);
        b2r[0] = t0.x; b2r[1] = t0.y; b2r[2] = t0.z; b2r[3] = t0.w;
        b2r[4] = t1.x; b2r[5] = t1.y; b2r[6] = t1.z; b2r[7] = t1.w;
        float4 u0 = *(const float4*)(tau); float4 u1 = *(const float4*)(tau + 4);
        taur[0] = u0.x; taur[1] = u0.y; taur[2] = u0.z; taur[3] = u0.w;
        taur[4] = u1.x; taur[5] = u1.y; taur[6] = u1.z; taur[7] = u1.w;
    }

    // 32 warps x 4 rows each
#pragma unroll
    for (int i = 0; i < 4; ++i) {
        const int lr = warp * 4 + i;
        const int r  = row0 + lr;
        const float* hr = hs + (size_t)lr * HS_STRIDE + c0;
        float h[8];
        {
            float4 t0 = *(const float4*)(hr);
            float4 t1 = *(const float4*)(hr + 4);
            h[0] = t0.x; h[1] = t0.y; h[2] = t0.z; h[3] = t0.w;
            h[4] = t1.x; h[5] = t1.y; h[6] = t1.z; h[7] = t1.w;
        }
        *(float4*)(out_h + (size_t)r * 256 + c0)     = make_float4(h[0], h[1], h[2], h[3]);
        *(float4*)(out_h + (size_t)r * 256 + c0 + 4) = make_float4(h[4], h[5], h[6], h[7]);

        float p[8];
        partial_logits(w2s, h, c0, p);
        butterfly_reduce8(p);

        if (lane == i) {
            float lg[8];
#pragma unroll
            for (int c = 0; c < 8; ++c) lg[c] = p[c] + b2r[c];
            float m = lg[0];
#pragma unroll
            for (int c = 1; c < 8; ++c) m = fmaxf(m, lg[c]);
            float e[8]; float s = 0.f;
#pragma unroll
            for (int c = 0; c < 8; ++c) { e[c] = expf(lg[c] - m); s += e[c]; }
            const float inv = 1.0f / s;
            int best = -1; float bv = -1.0f;
#pragma unroll
            for (int c = 0; c < 8; ++c) {
                float pr = e[c] * inv;
                if (pr >= taur[c] && pr > bv) { bv = pr; best = c; }
            }
            *(float4*)(out_logits + (size_t)r * 8)     = make_float4(lg[0], lg[1], lg[2], lg[3]);
            *(float4*)(out_logits + (size_t)r * 8 + 4) = make_float4(lg[4], lg[5], lg[6], lg[7]);
            out_depth[r] = (best >= 0) ? 1.0f : 0.0f;
            if (best >= 0) {
                int pos = atomicAdd(&scnt[best], 1);
                srows[best * 128 + pos] = r;
            }
        }
    }

    __syncthreads();
    if (tid < 8) sbase[tid] = atomicAdd(&g_cnt[tid], scnt[tid]);
    __syncthreads();
    if (tid < 8 * 128) {
        int e2 = tid >> 7, i2 = tid & 127;
        if (i2 < scnt[e2]) g_rows[e2 * B_N + sbase[e2] + i2] = srows[e2 * 128 + i2];
    }
}

// ---------------------------------------------------------------------------
// Kernel 2: per-expert gathered GEMM (pipelined); overwrites routed rows
// ---------------------------------------------------------------------------
__global__ void __launch_bounds__(1024, 1) expert_kernel(
    const float* __restrict__ bc1, const float* __restrict__ Wc2,
    const float* __restrict__ bc2,
    float* out_logits, float* out_h)
{
    const int c = blockIdx.y;
    const int cnt = g_cnt[c];
    const int start = blockIdx.x * 128;
    if (start >= cnt) return;
    const int n = min(128, cnt - start);

    extern __shared__ char sm[];
    const uint32_t smb = smem_to_u32(sm);
    const int tid = threadIdx.x, lane = tid & 31, warp = tid >> 5;
    const int c0 = lane * 8;

    float* w2s = (float*)(sm + W2S_OFF);
    float* bs1 = (float*)(sm + BS1_OFF);
    int* sidx  = (int*)(sm + SCNT_OFF);

    if (tid < 128) {
        int t = tid < n ? tid : (n - 1);    // tail pad with valid row (never stored)
        sidx[tid] = g_rows[c * B_N + start + t];
    }
    if (tid < 512) *(float4*)(w2s + tid * 4) = *(const float4*)(Wc2 + (size_t)c * 2048 + tid * 4);
    if (tid < 64)  *(float4*)(bs1 + tid * 4) = *(const float4*)(bc1 + (size_t)c * 256 + tid * 4);
    __syncthreads();

    float acc[2][4][4];
#pragma unroll
    for (int i = 0; i < 2; ++i)
#pragma unroll
        for (int j = 0; j < 4; ++j)
#pragma unroll
            for (int q = 0; q < 4; ++q) acc[i][j][q] = 0.f;

    const size_t moff = (size_t)(1 + c) * 65536;
    mma_pipeline<true>(out_h, g_Bh + moff, g_Bl + moff, sm, smb, sidx, 0, acc);

    __syncthreads();
    epilogue_stage_hs(sm, acc, bs1);
    __syncthreads();

    const float* hs = (const float*)sm;

    float b2r[8];
    {
        float4 t0 = *(const float4*)(bc2 + c * 8);
        float4 t1 = *(const float4*)(bc2 + c * 8 + 4);
        b2r[0] = t0.x; b2r[1] = t0.y; b2r[2] = t0.z; b2r[3] = t0.w;
        b2r[4] = t1.x; b2r[5] = t1.y; b2r[6] = t1.z; b2r[7] = t1.w;
    }

#pragma unroll
    for (int i = 0; i < 4; ++i) {
        const int lr = warp * 4 + i;
        const bool valid = lr < n;
        const int r = sidx[lr];
        const float* hr = hs + (size_t)lr * HS_STRIDE + c0;
        float h[8];
        {
            float4 t0 = *(const float4*)(hr);
            float4 t1 = *(const float4*)(hr + 4);
            h[0] = t0.x; h[1] = t0.y; h[2] = t0.z; h[3] = t0.w;
            h[4] = t1.x; h[5] = t1.y; h[6] = t1.z; h[7] = t1.w;
        }
        if (valid) {
            *(float4*)(out_h + (size_t)r * 256 + c0)     = make_float4(h[0], h[1], h[2], h[3]);
            *(float4*)(out_h + (size_t)r * 256 + c0 + 4) = make_float4(h[4], h[5], h[6], h[7]);
        }
        float p[8];
        partial_logits(w2s, h, c0, p);
        butterfly_reduce8(p);
        if (lane == i && valid) {
            float lg[8];
#pragma unroll
            for (int cc = 0; cc < 8; ++cc) lg[cc] = p[cc] + b2r[cc];
            *(float4*)(out_logits + (size_t)r * 8)     = make_float4(lg[0], lg[1], lg[2], lg[3]);
            *(float4*)(out_logits + (size_t)r * 8 + 4) = make_float4(lg[4], lg[5], lg[6], lg[7]);
        }
    }
}

// ---------------------------------------------------------------------------
// Launcher (graph-capturable: kernel launches only)
// ---------------------------------------------------------------------------
extern "C" void kernel_launch(void* const* d_in, const int* in_sizes, int n_in,
                              void* d_out, int out_size)
{
    const float* x   = (const float*)d_in[0];
    const float* W1  = (const float*)d_in[1];
    const float* b1  = (const float*)d_in[2];
    const float* W2  = (const float*)d_in[3];
    const float* b2  = (const float*)d_in[4];
    const float* Wc1 = (const float*)d_in[5];
    const float* bc1 = (const float*)d_in[6];
    const float* Wc2 = (const float*)d_in[7];
    const float* bc2 = (const float*)d_in[8];
    const float* tau = (const float*)d_in[9];

    float* out        = (float*)d_out;
    float* out_logits = out;
    float* out_h      = out + (size_t)B_N * C_N;
    float* out_depth  = out + (size_t)B_N * C_N + (size_t)B_N * H_N;

    cudaFuncSetAttribute(root_kernel,   cudaFuncAttributeMaxDynamicSharedMemorySize, SMEM_BYTES);
    cudaFuncSetAttribute(expert_kernel, cudaFuncAttributeMaxDynamicSharedMemorySize, SMEM_BYTES);

    prep_kernel<<<(9 * 65536 + 511) / 512, 512>>>(W1, Wc1);
    reset_kernel<<<1, 32>>>();
    root_kernel<<<B_N / 128, 1024, SMEM_BYTES>>>(
        x, b1, W2, b2, tau, out_logits, out_h, out_depth);
    expert_kernel<<<dim3(B_N / 128, C_N), 1024, SMEM_BYTES>>>(
        bc1, Wc2, bc2, out_logits, out_h);
}